// round 1
// baseline (speedup 1.0000x reference)
#include <cuda_runtime.h>
#include <cuda_bf16.h>
#include <math.h>

// ---------------------------------------------------------------------------
// Problem constants
// ---------------------------------------------------------------------------
#define IMG     512
#define PATCH   16
#define DIM     768
#define DEPTH   12
#define HEADS   12
#define HD      64
#define WIN     14
#define GRID_T  32              // tokens per side (512/16)
#define NTOK    (GRID_T*GRID_T) // 1024
#define OUTC    256
#define SCALE   0.125f          // 64^-0.5

// window partition: pad 32 -> 42, 3x3 windows of 14x14
#define NWIN    9
#define WTOK    (WIN*WIN)       // 196
#define MTOT    (NWIN*WTOK)     // 1764 padded-window tokens

// ---------------------------------------------------------------------------
// Device scratch (static: no allocation allowed)
// ---------------------------------------------------------------------------
__device__ float g_h     [NTOK * DIM];          // residual stream
__device__ float g_t     [NTOK * DIM];          // LN output
__device__ float g_win   [MTOT * DIM];          // window-partitioned tokens
__device__ float g_qkv   [MTOT * 3 * DIM];      // qkv projection output
__device__ float g_attn  [MTOT * DIM];          // attention output (head-merged)
__device__ float g_proj  [MTOT * DIM];          // proj / fc2 output
__device__ float g_mlp   [NTOK * 4 * DIM];      // fc1 output
__device__ float g_neck1 [NTOK * OUTC];
__device__ float g_neck2 [NTOK * OUTC];

// ---------------------------------------------------------------------------
// Patch embed: 16x16 stride-16 conv + bias + pos_embed
//   x: (3,512,512) NCHW   w: (16,16,3,768) HWIO   out: (1024,768)
// ---------------------------------------------------------------------------
__global__ void patch_kernel(const float* __restrict__ x,
                             const float* __restrict__ w,
                             const float* __restrict__ bias,
                             const float* __restrict__ pos,
                             float* __restrict__ out)
{
    int token = blockIdx.x;                 // 0..1023
    int gy = token >> 5, gx = token & 31;
    __shared__ float xs[PATCH*PATCH*3];     // (ph,pw,c) order matching w
    for (int i = threadIdx.x; i < PATCH*PATCH*3; i += blockDim.x) {
        int ph = i / 48, rem = i % 48;
        int pw = rem / 3, c = rem % 3;
        xs[i] = x[((size_t)c*IMG + gy*PATCH + ph)*IMG + gx*PATCH + pw];
    }
    __syncthreads();
    for (int d = threadIdx.x; d < DIM; d += blockDim.x) {
        float acc = bias[d] + pos[(size_t)token*DIM + d];
        #pragma unroll 4
        for (int i = 0; i < PATCH*PATCH*3; i++)
            acc += xs[i] * w[(size_t)i*DIM + d];
        out[(size_t)token*DIM + d] = acc;
    }
}

// ---------------------------------------------------------------------------
// LayerNorm over last dim C (one block per token)
// ---------------------------------------------------------------------------
__global__ void ln_kernel(const float* __restrict__ in,
                          const float* __restrict__ w,
                          const float* __restrict__ b,
                          float* __restrict__ out,
                          int C, float eps)
{
    int tok = blockIdx.x;
    const float* row = in + (size_t)tok * C;
    __shared__ float red[256];
    int tid = threadIdx.x;

    float s = 0.f;
    for (int c = tid; c < C; c += blockDim.x) s += row[c];
    red[tid] = s; __syncthreads();
    for (int st = 128; st > 0; st >>= 1) { if (tid < st) red[tid] += red[tid+st]; __syncthreads(); }
    float mean = red[0] / C;
    __syncthreads();

    float v = 0.f;
    for (int c = tid; c < C; c += blockDim.x) { float d = row[c] - mean; v += d*d; }
    red[tid] = v; __syncthreads();
    for (int st = 128; st > 0; st >>= 1) { if (tid < st) red[tid] += red[tid+st]; __syncthreads(); }
    float inv = rsqrtf(red[0] / C + eps);

    for (int c = tid; c < C; c += blockDim.x)
        out[(size_t)tok*C + c] = (row[c] - mean) * inv * w[c] + b[c];
}

// LN over OUTC channels per pixel + write transposed (C,H,W) to final output
__global__ void ln_transpose_kernel(const float* __restrict__ in,
                                    const float* __restrict__ w,
                                    const float* __restrict__ b,
                                    float* __restrict__ out,
                                    float eps)
{
    int pix = blockIdx.x;                   // 0..1023
    const float* row = in + (size_t)pix * OUTC;
    __shared__ float red[256];
    int tid = threadIdx.x;

    float s = (tid < OUTC) ? row[tid] : 0.f;
    red[tid] = s; __syncthreads();
    for (int st = 128; st > 0; st >>= 1) { if (tid < st) red[tid] += red[tid+st]; __syncthreads(); }
    float mean = red[0] / OUTC;
    __syncthreads();

    float d = (tid < OUTC) ? row[tid] - mean : 0.f;
    red[tid] = d*d; __syncthreads();
    for (int st = 128; st > 0; st >>= 1) { if (tid < st) red[tid] += red[tid+st]; __syncthreads(); }
    float inv = rsqrtf(red[0] / OUTC + eps);

    if (tid < OUTC)
        out[(size_t)tid * NTOK + pix] = d * inv * w[tid] + b[tid];
}

// ---------------------------------------------------------------------------
// SGEMM: C[M,N] = A[M,K] @ B[K,N] (+ bias[N])
// 64x64 tile, BK=16, 16x16 threads, 4x4 micro-tile
// ---------------------------------------------------------------------------
#define BM 64
#define BN 64
#define BK 16
__global__ void sgemm_kernel(const float* __restrict__ A,
                             const float* __restrict__ B,
                             const float* __restrict__ bias,
                             float* __restrict__ C,
                             int M, int N, int K)
{
    __shared__ float As[BK][BM];
    __shared__ float Bs[BK][BN];
    int tx = threadIdx.x, ty = threadIdx.y;
    int tid = ty * 16 + tx;
    int row0 = blockIdx.y * BM;
    int col0 = blockIdx.x * BN;

    float acc[4][4] = {};

    for (int k0 = 0; k0 < K; k0 += BK) {
        // load A tile (BM x BK) transposed into As[k][r]
        #pragma unroll
        for (int i = tid; i < BM*BK; i += 256) {
            int r = i / BK, k = i % BK;
            int gr = row0 + r;
            As[k][r] = (gr < M) ? A[(size_t)gr*K + k0 + k] : 0.f;
        }
        // load B tile (BK x BN)
        #pragma unroll
        for (int i = tid; i < BK*BN; i += 256) {
            int k = i / BN, c = i % BN;
            int gc = col0 + c;
            Bs[k][c] = (gc < N) ? B[(size_t)(k0+k)*N + gc] : 0.f;
        }
        __syncthreads();
        #pragma unroll
        for (int k = 0; k < BK; k++) {
            float a[4], bb[4];
            #pragma unroll
            for (int m = 0; m < 4; m++) a[m]  = As[k][ty*4 + m];
            #pragma unroll
            for (int n = 0; n < 4; n++) bb[n] = Bs[k][tx*4 + n];
            #pragma unroll
            for (int m = 0; m < 4; m++)
                #pragma unroll
                for (int n = 0; n < 4; n++)
                    acc[m][n] += a[m] * bb[n];
        }
        __syncthreads();
    }

    #pragma unroll
    for (int m = 0; m < 4; m++) {
        int gr = row0 + ty*4 + m;
        if (gr >= M) continue;
        #pragma unroll
        for (int n = 0; n < 4; n++) {
            int gc = col0 + tx*4 + n;
            if (gc >= N) continue;
            float v = acc[m][n];
            if (bias) v += bias[gc];
            C[(size_t)gr*N + gc] = v;
        }
    }
}

static inline void sgemm(const float* A, const float* B, const float* bias,
                         float* C, int M, int N, int K)
{
    dim3 grid((N + BN - 1)/BN, (M + BM - 1)/BM);
    sgemm_kernel<<<grid, dim3(16,16)>>>(A, B, bias, C, M, N, K);
}

// ---------------------------------------------------------------------------
// Window partition (32,32,768) -> (9,196,768) with zero pad to 42x42
// ---------------------------------------------------------------------------
__global__ void win_part_kernel(const float* __restrict__ in, float* __restrict__ out)
{
    int idx = blockIdx.x * blockDim.x + threadIdx.x;
    if (idx >= MTOT * DIM) return;
    int c   = idx % DIM;
    int row = idx / DIM;              // 0..1763
    int win = row / WTOK, r = row % WTOK;
    int wy = win / 3, wx = win % 3;
    int iy = wy*WIN + r/WIN;
    int ix = wx*WIN + r%WIN;
    out[idx] = (iy < GRID_T && ix < GRID_T) ? in[((size_t)iy*GRID_T + ix)*DIM + c] : 0.f;
}

// Un-partition + residual add into h
__global__ void win_unpart_add_kernel(const float* __restrict__ src, float* __restrict__ h)
{
    int idx = blockIdx.x * blockDim.x + threadIdx.x;
    if (idx >= NTOK * DIM) return;
    int c   = idx % DIM;
    int tok = idx / DIM;
    int gy = tok >> 5, gx = tok & 31;
    int win = (gy/WIN)*3 + gx/WIN;
    int r   = (gy%WIN)*WIN + gx%WIN;
    h[idx] += src[((size_t)win*WTOK + r)*DIM + c];
}

__global__ void add_kernel(float* __restrict__ dst, const float* __restrict__ src, int n)
{
    int i = blockIdx.x * blockDim.x + threadIdx.x;
    if (i < n) dst[i] += src[i];
}

__global__ void gelu_kernel(float* __restrict__ x, int n)
{
    int i = blockIdx.x * blockDim.x + threadIdx.x;
    if (i < n) {
        float v = x[i];
        x[i] = 0.5f * v * (1.f + erff(v * 0.70710678118654752f));
    }
}

// ---------------------------------------------------------------------------
// Attention: one block per (batch*head, query) row.
// qkv: (B*N, 3*DIM) with per-token layout [3][HEADS][HD]
// decomposed rel-pos bias precomputed into rh[kh], rw[kw]
// out: (B*N, DIM) with head-merged layout [HEADS][HD]
// ---------------------------------------------------------------------------
__global__ void attn_kernel(const float* __restrict__ qkv,
                            const float* __restrict__ rel_h,
                            const float* __restrict__ rel_w,
                            float* __restrict__ out,
                            int N, int H, int W)
{
    __shared__ float scores[1024];
    __shared__ float qs[HD];
    __shared__ float rh[32], rw[32];
    __shared__ float red[128];

    int qi = blockIdx.x;
    int bh = blockIdx.y;
    int b = bh / HEADS, hd = bh % HEADS;
    int tid = threadIdx.x;                // 128

    size_t base = (size_t)b * N * (3*DIM);
    const float* qrow = qkv + base + (size_t)qi*(3*DIM) + hd*HD;
    if (tid < HD) qs[tid] = qrow[tid];
    __syncthreads();

    int qy = qi / W, qx = qi % W;
    // rel-pos dot vectors
    for (int idx = tid; idx < H + W; idx += 128) {
        const float* rp;
        if (idx < H) rp = rel_h + (size_t)(qy - idx + H - 1) * HD;
        else         rp = rel_w + (size_t)(qx - (idx - H) + W - 1) * HD;
        float s = 0.f;
        #pragma unroll
        for (int c = 0; c < HD; c++) s += qs[c] * rp[c];
        if (idx < H) rh[idx] = s; else rw[idx - H] = s;
    }
    __syncthreads();

    // scores + max
    float lmax = -1e30f;
    for (int j = tid; j < N; j += 128) {
        const float* kr = qkv + base + (size_t)j*(3*DIM) + DIM + hd*HD;
        float s = 0.f;
        #pragma unroll
        for (int c = 0; c < HD; c++) s += qs[c] * kr[c];
        s = s * SCALE + rh[j / W] + rw[j % W];
        scores[j] = s;
        lmax = fmaxf(lmax, s);
    }
    red[tid] = lmax; __syncthreads();
    for (int st = 64; st > 0; st >>= 1) { if (tid < st) red[tid] = fmaxf(red[tid], red[tid+st]); __syncthreads(); }
    float m = red[0];
    __syncthreads();

    // exp + sum
    float lsum = 0.f;
    for (int j = tid; j < N; j += 128) {
        float e = expf(scores[j] - m);
        scores[j] = e;
        lsum += e;
    }
    red[tid] = lsum; __syncthreads();
    for (int st = 64; st > 0; st >>= 1) { if (tid < st) red[tid] += red[tid+st]; __syncthreads(); }
    float inv = 1.f / red[0];
    __syncthreads();

    // out = (scores @ V) * inv ; 128 threads = 2 halves x 64 channels
    int c = tid & 63, half = tid >> 6;
    const float* vb = qkv + base + 2*DIM + hd*HD + c;
    float acc = 0.f;
    for (int j = half; j < N; j += 2)
        acc += scores[j] * vb[(size_t)j*(3*DIM)];
    red[tid] = acc; __syncthreads();
    if (tid < HD)
        out[((size_t)b*N + qi)*DIM + hd*HD + tid] = (red[tid] + red[tid+64]) * inv;
}

// ---------------------------------------------------------------------------
// Neck conv3x3 SAME: in (32,32,256) NHWC, w (3,3,256,256), out (32,32,256)
// ---------------------------------------------------------------------------
__global__ void conv3x3_kernel(const float* __restrict__ in,
                               const float* __restrict__ w,
                               float* __restrict__ out)
{
    int pix = blockIdx.x;                 // 0..1023
    int oc  = threadIdx.x;                // 0..255
    int y = pix >> 5, x = pix & 31;
    float acc = 0.f;
    #pragma unroll
    for (int dy = 0; dy < 3; dy++) {
        int iy = y + dy - 1;
        if (iy < 0 || iy >= GRID_T) continue;
        #pragma unroll
        for (int dx = 0; dx < 3; dx++) {
            int ix = x + dx - 1;
            if (ix < 0 || ix >= GRID_T) continue;
            const float* ip = in + ((size_t)iy*GRID_T + ix) * OUTC;
            const float* wp = w + ((size_t)(dy*3 + dx) * OUTC) * OUTC + oc;
            #pragma unroll 8
            for (int ic = 0; ic < OUTC; ic++)
                acc += ip[ic] * wp[(size_t)ic * OUTC];
        }
    }
    out[(size_t)pix*OUTC + oc] = acc;
}

// ---------------------------------------------------------------------------
// Host orchestration
// ---------------------------------------------------------------------------
extern "C" void kernel_launch(void* const* d_in, const int* in_sizes, int n_in,
                              void* d_out, int out_size)
{
    (void)in_sizes; (void)n_in; (void)out_size;
    const float* x        = (const float*)d_in[0];
    const float* patch_w  = (const float*)d_in[1];
    const float* patch_b  = (const float*)d_in[2];
    const float* pos      = (const float*)d_in[3];
    const float* ln1_w    = (const float*)d_in[4];
    const float* ln1_b    = (const float*)d_in[5];
    const float* qkv_w    = (const float*)d_in[6];
    const float* qkv_b    = (const float*)d_in[7];
    const float* proj_w   = (const float*)d_in[8];
    const float* proj_b   = (const float*)d_in[9];
    const float* ln2_w    = (const float*)d_in[10];
    const float* ln2_b    = (const float*)d_in[11];
    const float* fc1_w    = (const float*)d_in[12];
    const float* fc1_b    = (const float*)d_in[13];
    const float* fc2_w    = (const float*)d_in[14];
    const float* fc2_b    = (const float*)d_in[15];
    const float* rhw      = (const float*)d_in[16]; // rel_h_win (8,27,64)
    const float* rww      = (const float*)d_in[17]; // rel_w_win
    const float* rhg      = (const float*)d_in[18]; // rel_h_glob (4,63,64)
    const float* rwg      = (const float*)d_in[19]; // rel_w_glob
    const float* neck_w1  = (const float*)d_in[20];
    const float* nln1_w   = (const float*)d_in[21];
    const float* nln1_b   = (const float*)d_in[22];
    const float* neck_w2  = (const float*)d_in[23];
    const float* nln2_w   = (const float*)d_in[24];
    const float* nln2_b   = (const float*)d_in[25];

    float *h, *t, *win, *qkv, *attn, *proj, *mlp, *neck1, *neck2;
    cudaGetSymbolAddress((void**)&h,     g_h);
    cudaGetSymbolAddress((void**)&t,     g_t);
    cudaGetSymbolAddress((void**)&win,   g_win);
    cudaGetSymbolAddress((void**)&qkv,   g_qkv);
    cudaGetSymbolAddress((void**)&attn,  g_attn);
    cudaGetSymbolAddress((void**)&proj,  g_proj);
    cudaGetSymbolAddress((void**)&mlp,   g_mlp);
    cudaGetSymbolAddress((void**)&neck1, g_neck1);
    cudaGetSymbolAddress((void**)&neck2, g_neck2);

    patch_kernel<<<NTOK, 256>>>(x, patch_w, patch_b, pos, h);

    int wi = 0, gi = 0;
    for (int i = 0; i < DEPTH; i++) {
        bool is_global = (i == 2 || i == 5 || i == 8 || i == 11);

        ln_kernel<<<NTOK, 256>>>(h, ln1_w + i*DIM, ln1_b + i*DIM, t, DIM, 1e-5f);

        int B, N, Hn, Wn, M;
        const float *relh, *relw, *Ain;
        if (is_global) {
            B = 1; N = NTOK; Hn = Wn = GRID_T; M = NTOK;
            relh = rhg + (size_t)gi * (2*GRID_T - 1) * HD;
            relw = rwg + (size_t)gi * (2*GRID_T - 1) * HD;
            gi++;
            Ain = t;
        } else {
            B = NWIN; N = WTOK; Hn = Wn = WIN; M = MTOT;
            win_part_kernel<<<(MTOT*DIM + 255)/256, 256>>>(t, win);
            relh = rhw + (size_t)wi * (2*WIN - 1) * HD;
            relw = rww + (size_t)wi * (2*WIN - 1) * HD;
            wi++;
            Ain = win;
        }

        sgemm(Ain, qkv_w + (size_t)i*DIM*3*DIM, qkv_b + (size_t)i*3*DIM, qkv, M, 3*DIM, DIM);
        attn_kernel<<<dim3(N, B*HEADS), 128>>>(qkv, relh, relw, attn, N, Hn, Wn);
        sgemm(attn, proj_w + (size_t)i*DIM*DIM, proj_b + (size_t)i*DIM, proj, M, DIM, DIM);

        if (is_global)
            add_kernel<<<(NTOK*DIM + 255)/256, 256>>>(h, proj, NTOK*DIM);
        else
            win_unpart_add_kernel<<<(NTOK*DIM + 255)/256, 256>>>(proj, h);

        ln_kernel<<<NTOK, 256>>>(h, ln2_w + i*DIM, ln2_b + i*DIM, t, DIM, 1e-5f);
        sgemm(t, fc1_w + (size_t)i*DIM*4*DIM, fc1_b + (size_t)i*4*DIM, mlp, NTOK, 4*DIM, DIM);
        gelu_kernel<<<(NTOK*4*DIM + 255)/256, 256>>>(mlp, NTOK*4*DIM);
        sgemm(mlp, fc2_w + (size_t)i*4*DIM*DIM, fc2_b + (size_t)i*DIM, proj, NTOK, DIM, 4*DIM);
        add_kernel<<<(NTOK*DIM + 255)/256, 256>>>(h, proj, NTOK*DIM);
    }

    // neck
    sgemm(h, neck_w1, nullptr, neck1, NTOK, OUTC, DIM);
    ln_kernel<<<NTOK, 256>>>(neck1, nln1_w, nln1_b, neck2, OUTC, 1e-6f);
    conv3x3_kernel<<<NTOK, OUTC>>>(neck2, neck_w2, neck1);
    ln_transpose_kernel<<<NTOK, 256>>>(neck1, nln2_w, nln2_b, (float*)d_out, 1e-6f);
}

// round 3
// speedup vs baseline: 3.4062x; 3.4062x over previous
#include <cuda_runtime.h>
#include <cuda_bf16.h>
#include <math.h>

// ---------------------------------------------------------------------------
// Problem constants
// ---------------------------------------------------------------------------
#define IMG     512
#define PATCH   16
#define DIM     768
#define TDIM    2304            // 3*DIM
#define DEPTH   12
#define HEADS   12
#define HD      64
#define WIN     14
#define GRID_T  32
#define NTOK    (GRID_T*GRID_T) // 1024
#define OUTC    256
#define SCALE   0.125f

#define NWIN    9
#define WTOK    (WIN*WIN)       // 196
#define MTOT    (NWIN*WTOK)     // 1764

// ---------------------------------------------------------------------------
// Device scratch
// ---------------------------------------------------------------------------
__device__ float g_h     [NTOK * DIM];
__device__ float g_t     [NTOK * DIM];
__device__ float g_win   [MTOT * DIM];
__device__ float g_qkv   [MTOT * TDIM];
__device__ float g_attn  [MTOT * DIM];
__device__ float g_proj  [MTOT * DIM];
__device__ float g_mlp   [NTOK * 4 * DIM];
__device__ float g_S     [12 * 1024 * 1024];    // scores scratch (max global case)
__device__ float g_rhv   [12 * 1024 * 32];      // per-(bh,q) rel-h dot vectors
__device__ float g_rwv   [12 * 1024 * 32];
__device__ float g_neck1 [NTOK * OUTC];
__device__ float g_neck2 [NTOK * OUTC];

// ---------------------------------------------------------------------------
// Patch embed
// ---------------------------------------------------------------------------
__global__ void patch_kernel(const float* __restrict__ x,
                             const float* __restrict__ w,
                             const float* __restrict__ bias,
                             const float* __restrict__ pos,
                             float* __restrict__ out)
{
    int token = blockIdx.x;
    int gy = token >> 5, gx = token & 31;
    __shared__ float xs[PATCH*PATCH*3];
    for (int i = threadIdx.x; i < PATCH*PATCH*3; i += blockDim.x) {
        int ph = i / 48, rem = i % 48;
        int pw = rem / 3, c = rem % 3;
        xs[i] = x[((size_t)c*IMG + gy*PATCH + ph)*IMG + gx*PATCH + pw];
    }
    __syncthreads();
    for (int d = threadIdx.x; d < DIM; d += blockDim.x) {
        float acc = bias[d] + pos[(size_t)token*DIM + d];
        #pragma unroll 4
        for (int i = 0; i < PATCH*PATCH*3; i++)
            acc += xs[i] * w[(size_t)i*DIM + d];
        out[(size_t)token*DIM + d] = acc;
    }
}

// ---------------------------------------------------------------------------
// LayerNorm
// ---------------------------------------------------------------------------
__global__ void ln_kernel(const float* __restrict__ in,
                          const float* __restrict__ w,
                          const float* __restrict__ b,
                          float* __restrict__ out,
                          int C, float eps)
{
    int tok = blockIdx.x;
    const float* row = in + (size_t)tok * C;
    __shared__ float red[256];
    int tid = threadIdx.x;

    float s = 0.f;
    for (int c = tid; c < C; c += blockDim.x) s += row[c];
    red[tid] = s; __syncthreads();
    for (int st = 128; st > 0; st >>= 1) { if (tid < st) red[tid] += red[tid+st]; __syncthreads(); }
    float mean = red[0] / C;
    __syncthreads();

    float v = 0.f;
    for (int c = tid; c < C; c += blockDim.x) { float d = row[c] - mean; v += d*d; }
    red[tid] = v; __syncthreads();
    for (int st = 128; st > 0; st >>= 1) { if (tid < st) red[tid] += red[tid+st]; __syncthreads(); }
    float inv = rsqrtf(red[0] / C + eps);

    for (int c = tid; c < C; c += blockDim.x)
        out[(size_t)tok*C + c] = (row[c] - mean) * inv * w[c] + b[c];
}

__global__ void ln_transpose_kernel(const float* __restrict__ in,
                                    const float* __restrict__ w,
                                    const float* __restrict__ b,
                                    float* __restrict__ out,
                                    float eps)
{
    int pix = blockIdx.x;
    const float* row = in + (size_t)pix * OUTC;
    __shared__ float red[256];
    int tid = threadIdx.x;

    float s = (tid < OUTC) ? row[tid] : 0.f;
    red[tid] = s; __syncthreads();
    for (int st = 128; st > 0; st >>= 1) { if (tid < st) red[tid] += red[tid+st]; __syncthreads(); }
    float mean = red[0] / OUTC;
    __syncthreads();

    float d = (tid < OUTC) ? row[tid] - mean : 0.f;
    red[tid] = d*d; __syncthreads();
    for (int st = 128; st > 0; st >>= 1) { if (tid < st) red[tid] += red[tid+st]; __syncthreads(); }
    float inv = rsqrtf(red[0] / OUTC + eps);

    if (tid < OUTC)
        out[(size_t)tid * NTOK + pix] = d * inv * w[tid] + b[tid];
}

// ---------------------------------------------------------------------------
// SGEMM v2: C[M,N] = A[M,K] @ B[K,N] (+bias, optional gelu)
// 64x64 tile, BK=16, 256 threads, 4x4 micro, double-buffered smem, float4 IO
// Requires: K % 16 == 0, N % 64 == 0
// ---------------------------------------------------------------------------
#define BM 64
#define BN 64
#define BK 16

__global__ __launch_bounds__(256) void sgemm2_kernel(
    const float* __restrict__ A, const float* __restrict__ B,
    const float* __restrict__ bias, float* __restrict__ C,
    int M, int N, int K, int gelu_flag)
{
    __shared__ float As[2][BK][BM+4];
    __shared__ float Bs[2][BK][BN];
    int tid = threadIdx.x;
    int tx = tid & 15, ty = tid >> 4;
    int row0 = blockIdx.y * BM, col0 = blockIdx.x * BN;

    int ar = tid >> 2;            // 0..63 (A row within tile)
    int ak = (tid & 3) * 4;       // 0,4,8,12
    int bk = tid >> 4;            // 0..15
    int bc = (tid & 15) * 4;

    const float* Aptr = A + (size_t)(row0 + ar) * K + ak;
    const float* Bptr = B + (size_t)bk * N + col0 + bc;
    bool a_ok = (row0 + ar) < M;

    float4 a_ld = a_ok ? *(const float4*)Aptr : make_float4(0,0,0,0);
    float4 b_ld = *(const float4*)Bptr;
    As[0][ak+0][ar] = a_ld.x; As[0][ak+1][ar] = a_ld.y;
    As[0][ak+2][ar] = a_ld.z; As[0][ak+3][ar] = a_ld.w;
    *(float4*)&Bs[0][bk][bc] = b_ld;
    __syncthreads();

    float acc[4][4] = {};
    int KT = K / BK;
    for (int kt = 0; kt < KT; kt++) {
        int cur = kt & 1;
        if (kt + 1 < KT) {
            a_ld = a_ok ? *(const float4*)(Aptr + (kt+1)*BK) : make_float4(0,0,0,0);
            b_ld = *(const float4*)(Bptr + (size_t)(kt+1)*BK*N);
        }
        #pragma unroll
        for (int k = 0; k < BK; k++) {
            float4 av = *(const float4*)&As[cur][k][ty*4];
            float4 bv = *(const float4*)&Bs[cur][k][tx*4];
            float am[4] = {av.x, av.y, av.z, av.w};
            float bn[4] = {bv.x, bv.y, bv.z, bv.w};
            #pragma unroll
            for (int m = 0; m < 4; m++)
                #pragma unroll
                for (int n = 0; n < 4; n++)
                    acc[m][n] += am[m] * bn[n];
        }
        if (kt + 1 < KT) {
            int nxt = cur ^ 1;
            As[nxt][ak+0][ar] = a_ld.x; As[nxt][ak+1][ar] = a_ld.y;
            As[nxt][ak+2][ar] = a_ld.z; As[nxt][ak+3][ar] = a_ld.w;
            *(float4*)&Bs[nxt][bk][bc] = b_ld;
        }
        __syncthreads();
    }

    float4 bv4 = bias ? *(const float4*)(bias + col0 + tx*4) : make_float4(0,0,0,0);
    #pragma unroll
    for (int m = 0; m < 4; m++) {
        int gr = row0 + ty*4 + m;
        if (gr >= M) continue;
        float4 v;
        v.x = acc[m][0] + bv4.x; v.y = acc[m][1] + bv4.y;
        v.z = acc[m][2] + bv4.z; v.w = acc[m][3] + bv4.w;
        if (gelu_flag) {
            v.x = 0.5f*v.x*(1.f+erff(v.x*0.70710678118654752f));
            v.y = 0.5f*v.y*(1.f+erff(v.y*0.70710678118654752f));
            v.z = 0.5f*v.z*(1.f+erff(v.z*0.70710678118654752f));
            v.w = 0.5f*v.w*(1.f+erff(v.w*0.70710678118654752f));
        }
        *(float4*)(C + (size_t)gr*N + col0 + tx*4) = v;
    }
}

static inline void sgemm(const float* A, const float* B, const float* bias,
                         float* C, int M, int N, int K, int gelu = 0)
{
    dim3 grid(N / BN, (M + BM - 1) / BM);
    sgemm2_kernel<<<grid, 256>>>(A, B, bias, C, M, N, K, gelu);
}

// ---------------------------------------------------------------------------
// Window partition / unpartition
// ---------------------------------------------------------------------------
__global__ void win_part_kernel(const float* __restrict__ in, float* __restrict__ out)
{
    int idx = blockIdx.x * blockDim.x + threadIdx.x;
    if (idx >= MTOT * DIM) return;
    int c   = idx % DIM;
    int row = idx / DIM;
    int win = row / WTOK, r = row % WTOK;
    int wy = win / 3, wx = win % 3;
    int iy = wy*WIN + r/WIN;
    int ix = wx*WIN + r%WIN;
    out[idx] = (iy < GRID_T && ix < GRID_T) ? in[((size_t)iy*GRID_T + ix)*DIM + c] : 0.f;
}

__global__ void win_unpart_add_kernel(const float* __restrict__ src, float* __restrict__ h)
{
    int idx = blockIdx.x * blockDim.x + threadIdx.x;
    if (idx >= NTOK * DIM) return;
    int c   = idx % DIM;
    int tok = idx / DIM;
    int gy = tok >> 5, gx = tok & 31;
    int win = (gy/WIN)*3 + gx/WIN;
    int r   = (gy%WIN)*WIN + gx%WIN;
    h[idx] += src[((size_t)win*WTOK + r)*DIM + c];
}

__global__ void add_kernel(float* __restrict__ dst, const float* __restrict__ src, int n)
{
    int i = blockIdx.x * blockDim.x + threadIdx.x;
    if (i < n) dst[i] += src[i];
}

// ---------------------------------------------------------------------------
// Rel-pos dot vectors: rhv[bh,q,ky] = dot(Q[bh,q], Rh[qy,ky]), likewise rwv
// grid (N, BH), 64 threads
// ---------------------------------------------------------------------------
__global__ void relpos_kernel(const float* __restrict__ qkv,
                              const float* __restrict__ rel_h,
                              const float* __restrict__ rel_w,
                              float* __restrict__ rhv,
                              float* __restrict__ rwv,
                              int N, int H, int W)
{
    int qi = blockIdx.x;
    int bh = blockIdx.y;
    int b = bh / HEADS, head = bh % HEADS;
    int tid = threadIdx.x;
    __shared__ float qs[HD];

    const float* qrow = qkv + (size_t)(b*N + qi)*TDIM + head*HD;
    qs[tid] = qrow[tid];
    __syncthreads();

    int qy = qi / W, qx = qi % W;
    for (int idx = tid; idx < H + W; idx += 64) {
        const float* rp;
        if (idx < H) rp = rel_h + (size_t)(qy - idx + H - 1) * HD;
        else         rp = rel_w + (size_t)(qx - (idx - H) + W - 1) * HD;
        float s = 0.f;
        #pragma unroll
        for (int c = 0; c < HD; c++) s += qs[c] * rp[c];
        if (idx < H) rhv[((size_t)bh*N + qi)*H + idx] = s;
        else         rwv[((size_t)bh*N + qi)*W + (idx - H)] = s;
    }
}

// ---------------------------------------------------------------------------
// Scores: S[bh,q,k] = SCALE * dot(Q[bh,q], K[bh,k]) + rhv[q,ky] + rwv[q,kx]
// Batched NT GEMM, 64x64 tile, K=64. grid (ktile, qtile, BH)
// ---------------------------------------------------------------------------
__global__ __launch_bounds__(256) void scores_kernel(
    const float* __restrict__ qkv,
    const float* __restrict__ rhv, const float* __restrict__ rwv,
    float* __restrict__ S,
    int N, int H, int W)
{
    __shared__ float Qs[BK][BM+4];
    __shared__ float Ks[BK][BN+4];
    int tid = threadIdx.x;
    int tx = tid & 15, ty = tid >> 4;
    int bh = blockIdx.z;
    int b = bh / HEADS, head = bh % HEADS;
    int q0 = blockIdx.y * BM, k0 = blockIdx.x * BN;

    const float* Qb = qkv + (size_t)b*N*TDIM + head*HD;
    const float* Kb = Qb + DIM;

    int ar = tid >> 2;
    int ac = (tid & 3) * 4;

    float acc[4][4] = {};
    for (int c0 = 0; c0 < HD; c0 += BK) {
        float4 qv = (q0 + ar < N) ? *(const float4*)(Qb + (size_t)(q0+ar)*TDIM + c0 + ac)
                                  : make_float4(0,0,0,0);
        float4 kv = (k0 + ar < N) ? *(const float4*)(Kb + (size_t)(k0+ar)*TDIM + c0 + ac)
                                  : make_float4(0,0,0,0);
        Qs[ac+0][ar] = qv.x; Qs[ac+1][ar] = qv.y; Qs[ac+2][ar] = qv.z; Qs[ac+3][ar] = qv.w;
        Ks[ac+0][ar] = kv.x; Ks[ac+1][ar] = kv.y; Ks[ac+2][ar] = kv.z; Ks[ac+3][ar] = kv.w;
        __syncthreads();
        #pragma unroll
        for (int k = 0; k < BK; k++) {
            float4 av = *(const float4*)&Qs[k][ty*4];
            float4 bv = *(const float4*)&Ks[k][tx*4];
            float am[4] = {av.x, av.y, av.z, av.w};
            float bn[4] = {bv.x, bv.y, bv.z, bv.w};
            #pragma unroll
            for (int m = 0; m < 4; m++)
                #pragma unroll
                for (int n = 0; n < 4; n++)
                    acc[m][n] += am[m] * bn[n];
        }
        __syncthreads();
    }

    float* Sb = S + (size_t)bh * N * N;
    #pragma unroll
    for (int m = 0; m < 4; m++) {
        int q = q0 + ty*4 + m;
        if (q >= N) continue;
        const float* rh = rhv + ((size_t)bh*N + q)*H;
        const float* rw = rwv + ((size_t)bh*N + q)*W;
        #pragma unroll
        for (int n = 0; n < 4; n++) {
            int k = k0 + tx*4 + n;
            if (k >= N) continue;
            Sb[(size_t)q*N + k] = acc[m][n]*SCALE + rh[k/W] + rw[k%W];
        }
    }
}

// ---------------------------------------------------------------------------
// Row softmax on S: grid (N, BH), 128 threads
// ---------------------------------------------------------------------------
__global__ void softmax_kernel(float* __restrict__ S, int N)
{
    __shared__ float sc[1024];
    __shared__ float red[128];
    int q = blockIdx.x, bh = blockIdx.y;
    int tid = threadIdx.x;
    float* row = S + ((size_t)bh*N + q)*N;

    float lmax = -1e30f;
    for (int j = tid; j < N; j += 128) { float v = row[j]; sc[j] = v; lmax = fmaxf(lmax, v); }
    red[tid] = lmax; __syncthreads();
    for (int st = 64; st > 0; st >>= 1) { if (tid < st) red[tid] = fmaxf(red[tid], red[tid+st]); __syncthreads(); }
    float m = red[0];
    __syncthreads();

    float lsum = 0.f;
    for (int j = tid; j < N; j += 128) { float e = __expf(sc[j] - m); sc[j] = e; lsum += e; }
    red[tid] = lsum; __syncthreads();
    for (int st = 64; st > 0; st >>= 1) { if (tid < st) red[tid] += red[tid+st]; __syncthreads(); }
    float inv = 1.f / red[0];
    __syncthreads();

    for (int j = tid; j < N; j += 128) row[j] = sc[j] * inv;
}

// ---------------------------------------------------------------------------
// O = P @ V, batched NN GEMM, tile 64q x 64c, K-loop over N.
// grid (qtile, BH). Writes head-merged layout.
// ---------------------------------------------------------------------------
__global__ __launch_bounds__(256) void av_kernel(
    const float* __restrict__ S, const float* __restrict__ qkv,
    float* __restrict__ out, int N)
{
    __shared__ float Ps[BK][BM+4];
    __shared__ float Vs[BK][BN];
    int tid = threadIdx.x;
    int tx = tid & 15, ty = tid >> 4;
    int bh = blockIdx.y;
    int b = bh / HEADS, head = bh % HEADS;
    int q0 = blockIdx.x * BM;

    const float* Pb = S + (size_t)bh * N * N;
    const float* Vb = qkv + (size_t)b*N*TDIM + 2*DIM + head*HD;

    int ar = tid >> 2;
    int ak = (tid & 3) * 4;
    int vk = tid >> 4;
    int vc = (tid & 15) * 4;

    float acc[4][4] = {};
    int KT = (N + BK - 1) / BK;
    for (int kt = 0; kt < KT; kt++) {
        int k0 = kt * BK;
        float4 pv = (q0 + ar < N && k0 + ak < N)
                    ? *(const float4*)(Pb + (size_t)(q0+ar)*N + k0 + ak)
                    : make_float4(0,0,0,0);
        float4 vv = (k0 + vk < N)
                    ? *(const float4*)(Vb + (size_t)(k0+vk)*TDIM + vc)
                    : make_float4(0,0,0,0);
        Ps[ak+0][ar] = pv.x; Ps[ak+1][ar] = pv.y; Ps[ak+2][ar] = pv.z; Ps[ak+3][ar] = pv.w;
        *(float4*)&Vs[vk][vc] = vv;
        __syncthreads();
        #pragma unroll
        for (int k = 0; k < BK; k++) {
            float4 av = *(const float4*)&Ps[k][ty*4];
            float4 bv = *(const float4*)&Vs[k][tx*4];
            float am[4] = {av.x, av.y, av.z, av.w};
            float bn[4] = {bv.x, bv.y, bv.z, bv.w};
            #pragma unroll
            for (int m = 0; m < 4; m++)
                #pragma unroll
                for (int n = 0; n < 4; n++)
                    acc[m][n] += am[m] * bn[n];
        }
        __syncthreads();
    }

    #pragma unroll
    for (int m = 0; m < 4; m++) {
        int q = q0 + ty*4 + m;
        if (q >= N) continue;
        float4 v; v.x = acc[m][0]; v.y = acc[m][1]; v.z = acc[m][2]; v.w = acc[m][3];
        *(float4*)(out + (size_t)(b*N + q)*DIM + head*HD + tx*4) = v;
    }
}

// ---------------------------------------------------------------------------
// Neck conv3x3
// ---------------------------------------------------------------------------
__global__ void conv3x3_kernel(const float* __restrict__ in,
                               const float* __restrict__ w,
                               float* __restrict__ out)
{
    int pix = blockIdx.x;
    int oc  = threadIdx.x;
    int y = pix >> 5, x = pix & 31;
    float acc = 0.f;
    #pragma unroll
    for (int dy = 0; dy < 3; dy++) {
        int iy = y + dy - 1;
        if (iy < 0 || iy >= GRID_T) continue;
        #pragma unroll
        for (int dx = 0; dx < 3; dx++) {
            int ix = x + dx - 1;
            if (ix < 0 || ix >= GRID_T) continue;
            const float* ip = in + ((size_t)iy*GRID_T + ix) * OUTC;
            const float* wp = w + ((size_t)(dy*3 + dx) * OUTC) * OUTC + oc;
            #pragma unroll 8
            for (int ic = 0; ic < OUTC; ic++)
                acc += ip[ic] * wp[(size_t)ic * OUTC];
        }
    }
    out[(size_t)pix*OUTC + oc] = acc;
}

// ---------------------------------------------------------------------------
// Host orchestration
// ---------------------------------------------------------------------------
extern "C" void kernel_launch(void* const* d_in, const int* in_sizes, int n_in,
                              void* d_out, int out_size)
{
    (void)in_sizes; (void)n_in; (void)out_size;
    const float* x        = (const float*)d_in[0];
    const float* patch_w  = (const float*)d_in[1];
    const float* patch_b  = (const float*)d_in[2];
    const float* pos      = (const float*)d_in[3];
    const float* ln1_w    = (const float*)d_in[4];
    const float* ln1_b    = (const float*)d_in[5];
    const float* qkv_w    = (const float*)d_in[6];
    const float* qkv_b    = (const float*)d_in[7];
    const float* proj_w   = (const float*)d_in[8];
    const float* proj_b   = (const float*)d_in[9];
    const float* ln2_w    = (const float*)d_in[10];
    const float* ln2_b    = (const float*)d_in[11];
    const float* fc1_w    = (const float*)d_in[12];
    const float* fc1_b    = (const float*)d_in[13];
    const float* fc2_w    = (const float*)d_in[14];
    const float* fc2_b    = (const float*)d_in[15];
    const float* rhw      = (const float*)d_in[16];
    const float* rww      = (const float*)d_in[17];
    const float* rhg      = (const float*)d_in[18];
    const float* rwg      = (const float*)d_in[19];
    const float* neck_w1  = (const float*)d_in[20];
    const float* nln1_w   = (const float*)d_in[21];
    const float* nln1_b   = (const float*)d_in[22];
    const float* neck_w2  = (const float*)d_in[23];
    const float* nln2_w   = (const float*)d_in[24];
    const float* nln2_b   = (const float*)d_in[25];

    float *h, *t, *win, *qkv, *attn, *proj, *mlp, *S, *rhv, *rwv, *neck1, *neck2;
    cudaGetSymbolAddress((void**)&h,     g_h);
    cudaGetSymbolAddress((void**)&t,     g_t);
    cudaGetSymbolAddress((void**)&win,   g_win);
    cudaGetSymbolAddress((void**)&qkv,   g_qkv);
    cudaGetSymbolAddress((void**)&attn,  g_attn);
    cudaGetSymbolAddress((void**)&proj,  g_proj);
    cudaGetSymbolAddress((void**)&mlp,   g_mlp);
    cudaGetSymbolAddress((void**)&S,     g_S);
    cudaGetSymbolAddress((void**)&rhv,   g_rhv);
    cudaGetSymbolAddress((void**)&rwv,   g_rwv);
    cudaGetSymbolAddress((void**)&neck1, g_neck1);
    cudaGetSymbolAddress((void**)&neck2, g_neck2);

    patch_kernel<<<NTOK, 256>>>(x, patch_w, patch_b, pos, h);

    int wi = 0, gi = 0;
    for (int i = 0; i < DEPTH; i++) {
        bool is_global = (i == 2 || i == 5 || i == 8 || i == 11);

        ln_kernel<<<NTOK, 256>>>(h, ln1_w + i*DIM, ln1_b + i*DIM, t, DIM, 1e-5f);

        int B, N, Hn, Wn, M;
        const float *relh, *relw, *Ain;
        if (is_global) {
            B = 1; N = NTOK; Hn = Wn = GRID_T; M = NTOK;
            relh = rhg + (size_t)gi * (2*GRID_T - 1) * HD;
            relw = rwg + (size_t)gi * (2*GRID_T - 1) * HD;
            gi++;
            Ain = t;
        } else {
            B = NWIN; N = WTOK; Hn = Wn = WIN; M = MTOT;
            win_part_kernel<<<(MTOT*DIM + 255)/256, 256>>>(t, win);
            relh = rhw + (size_t)wi * (2*WIN - 1) * HD;
            relw = rww + (size_t)wi * (2*WIN - 1) * HD;
            wi++;
            Ain = win;
        }
        int BH = B * HEADS;
        int QT = (N + BM - 1) / BM;

        sgemm(Ain, qkv_w + (size_t)i*DIM*TDIM, qkv_b + (size_t)i*TDIM, qkv, M, TDIM, DIM);

        relpos_kernel<<<dim3(N, BH), 64>>>(qkv, relh, relw, rhv, rwv, N, Hn, Wn);
        scores_kernel<<<dim3(QT, QT, BH), 256>>>(qkv, rhv, rwv, S, N, Hn, Wn);
        softmax_kernel<<<dim3(N, BH), 128>>>(S, N);
        av_kernel<<<dim3(QT, BH), 256>>>(S, qkv, attn, N);

        sgemm(attn, proj_w + (size_t)i*DIM*DIM, proj_b + (size_t)i*DIM, proj, M, DIM, DIM);

        if (is_global)
            add_kernel<<<(NTOK*DIM + 255)/256, 256>>>(h, proj, NTOK*DIM);
        else
            win_unpart_add_kernel<<<(NTOK*DIM + 255)/256, 256>>>(proj, h);

        ln_kernel<<<NTOK, 256>>>(h, ln2_w + i*DIM, ln2_b + i*DIM, t, DIM, 1e-5f);
        sgemm(t, fc1_w + (size_t)i*DIM*4*DIM, fc1_b + (size_t)i*4*DIM, mlp, NTOK, 4*DIM, DIM, 1);
        sgemm(mlp, fc2_w + (size_t)i*4*DIM*DIM, fc2_b + (size_t)i*DIM, proj, NTOK, DIM, 4*DIM);
        add_kernel<<<(NTOK*DIM + 255)/256, 256>>>(h, proj, NTOK*DIM);
    }

    // neck
    sgemm(h, neck_w1, nullptr, neck1, NTOK, OUTC, DIM);
    ln_kernel<<<NTOK, 256>>>(neck1, nln1_w, nln1_b, neck2, OUTC, 1e-6f);
    conv3x3_kernel<<<NTOK, OUTC>>>(neck2, neck_w2, neck1);
    ln_transpose_kernel<<<NTOK, 256>>>(neck1, nln2_w, nln2_b, (float*)d_out, 1e-6f);
}